// round 1
// baseline (speedup 1.0000x reference)
#include <cuda_runtime.h>
#include <math.h>

// ---------------------------------------------------------------------------
// Improved_DSTGAT_Attn_Adaptive: fused EEG conv stack + 2-layer GAT on GB300
// Kernel plan:
//   k0_graph : build M multiplicity matrix -> g_elogM [64x64]     (1 block)
//   k1_feat  : fused conv1(K25)+BN+ELU, dwK3+BN+ELU, sdwK3, pw16x16+BN+ELU,
//              mean over T -> g_feats [8192x16]                   (8192 blocks)
//   k2_gat1  : per-batch GAT1 + BN + skip + GELU -> g_h1, partial SE sums
//   k4_gat2  : SE-gate1 (redundant per block), GAT2 + BN + res + GELU -> g_h2
//   k6_out   : SE-gate2, pool over nodes, classifier -> out [128x2]
// ---------------------------------------------------------------------------

#define NSEQ 8192
#define TLEN 500
#define H1S  504   // padded smem row stride for 16 x (500+pads)

__device__ float g_feats[NSEQ * 16];
__device__ float g_h1[NSEQ * 32];
__device__ float g_h2[NSEQ * 32];
__device__ float g_elogM[64 * 64];
__device__ float g_ps1[128 * 32];
__device__ float g_ps2[128 * 32];

__device__ __forceinline__ float eluf(float x)  { return x > 0.f ? x : expm1f(x); }
__device__ __forceinline__ float geluf(float x) { return 0.5f * x * (1.f + erff(x * 0.70710678118654752f)); }
__device__ __forceinline__ float lrelu(float x) { return x > 0.f ? x : 0.2f * x; }
__device__ __forceinline__ float sigm(float x)  { return 1.f / (1.f + expf(-x)); }

// ---------------------------------------------------------------------------
// K0: adjacency / multiplicity matrix -> log-mask
// ---------------------------------------------------------------------------
__global__ void k0_graph(const float* __restrict__ E, const int* __restrict__ ei)
{
    __shared__ float Es[64 * 16];
    __shared__ float As[64 * 65];
    __shared__ float den[64];
    __shared__ int   Ms[64 * 64];
    int tid = threadIdx.x;
    for (int i = tid; i < 1024; i += 256) Es[i] = E[i];
    for (int i = tid; i < 4096; i += 256) Ms[i] = 0;
    __syncthreads();
    for (int idx = tid; idx < 4096; idx += 256) {
        int i = idx >> 6, j = idx & 63;
        float a = 0.f;
        #pragma unroll
        for (int c = 0; c < 16; c++) a += Es[i * 16 + c] * Es[j * 16 + c];
        As[i * 65 + j] = a > 0.f ? a : 0.f;
    }
    __syncthreads();
    for (int i = tid; i < 64; i += 256) {
        float s = 0.f;
        for (int j = 0; j < 64; j++) s += As[i * 65 + j];
        den[i] = s + 1e-6f;
    }
    __syncthreads();
    if (tid < 256) {
        atomicAdd(&Ms[ei[tid] * 64 + ei[256 + tid]], 1);
    }
    __syncthreads();
    for (int idx = tid; idx < 4096; idx += 256) {
        int i = idx >> 6, j = idx & 63;
        float dyn = (As[i * 65 + j] / den[i] > 0.1f) ? 1.f : 0.f;
        float Mv  = (i == j) ? 1.f : ((float)Ms[idx] + dyn);
        g_elogM[idx] = (Mv > 0.f) ? logf(Mv) : -1e30f;
    }
}

// ---------------------------------------------------------------------------
// K1: fused feature extractor. One CTA per (b,c) sequence, 256 thr (8 warps),
// each warp owns 2 of the 16 channels. All intermediates in smem.
// ---------------------------------------------------------------------------
__global__ __launch_bounds__(256) void k1_feat(
    const float* __restrict__ x,
    const float* __restrict__ c1w,  const float* __restrict__ bn1,
    const float* __restrict__ dww,  const float* __restrict__ bn2,
    const float* __restrict__ sdww, const float* __restrict__ spww,
    const float* __restrict__ bn3)
{
    extern __shared__ float sm[];
    float* xs = sm;               // 528 (x padded by 12 each side, rounded)
    float* hA = sm + 528;         // 16 * 504
    float* hB = hA + 16 * H1S;    // 16 * 504
    int tid = threadIdx.x, warp = tid >> 5, lane = tid & 31;
    int seq = blockIdx.x;
    const float* xp = x + (size_t)seq * TLEN;

    for (int i = tid; i < 528; i += 256) {
        int t = i - 12;
        xs[i] = (t >= 0 && t < TLEN) ? xp[t] : 0.f;
    }
    if (tid < 16) {  // zero pads for the K=3 depthwise stages
        hA[tid * H1S] = 0.f; hA[tid * H1S + 501] = 0.f;
        hB[tid * H1S] = 0.f; hB[tid * H1S + 501] = 0.f;
    }

    int f0 = warp * 2, f1 = f0 + 1;

    // conv1 weights folded with BN1
    float sc0 = bn1[f0] * rsqrtf(bn1[48 + f0] + 1e-5f);
    float sc1 = bn1[f1] * rsqrtf(bn1[48 + f1] + 1e-5f);
    float b0  = bn1[16 + f0] - bn1[32 + f0] * sc0;
    float b1  = bn1[16 + f1] - bn1[32 + f1] * sc1;
    float w0[25], w1[25];
    #pragma unroll
    for (int k = 0; k < 25; k++) { w0[k] = c1w[f0 * 25 + k] * sc0; w1[k] = c1w[f1 * 25 + k] * sc1; }
    __syncthreads();

    // conv1 (K=25) + BN + ELU: 4 consecutive t per lane, float4 window loads
    for (int p = lane; p < 125; p += 32) {
        float xw[28];
        const float4* xq = ((const float4*)xs) + p;
        #pragma unroll
        for (int q = 0; q < 7; q++) {
            float4 v = xq[q];
            xw[4*q] = v.x; xw[4*q+1] = v.y; xw[4*q+2] = v.z; xw[4*q+3] = v.w;
        }
        float a0[4] = {b0, b0, b0, b0}, a1[4] = {b1, b1, b1, b1};
        #pragma unroll
        for (int k = 0; k < 25; k++) {
            #pragma unroll
            for (int s = 0; s < 4; s++) {
                float xv = xw[k + s];
                a0[s] += xv * w0[k];
                a1[s] += xv * w1[k];
            }
        }
        #pragma unroll
        for (int s = 0; s < 4; s++) {
            hA[f0 * H1S + 1 + 4*p + s] = eluf(a0[s]);
            hA[f1 * H1S + 1 + 4*p + s] = eluf(a1[s]);
        }
    }
    // (channel-local chain: warp owns both producer & consumer channels -> no sync)

    // depthwise K=3 + BN + ELU  (hA -> hB)
    float dsc0 = bn2[f0] * rsqrtf(bn2[48 + f0] + 1e-5f);
    float dsc1 = bn2[f1] * rsqrtf(bn2[48 + f1] + 1e-5f);
    float db0  = bn2[16 + f0] - bn2[32 + f0] * dsc0;
    float db1  = bn2[16 + f1] - bn2[32 + f1] * dsc1;
    float d0[3], d1[3];
    #pragma unroll
    for (int k = 0; k < 3; k++) { d0[k] = dww[f0 * 3 + k] * dsc0; d1[k] = dww[f1 * 3 + k] * dsc1; }
    for (int p = lane; p < 125; p += 32) {
        float v0[6], v1[6];
        #pragma unroll
        for (int q = 0; q < 6; q++) { v0[q] = hA[f0 * H1S + 4*p + q]; v1[q] = hA[f1 * H1S + 4*p + q]; }
        #pragma unroll
        for (int s = 0; s < 4; s++) {
            float o0 = db0, o1 = db1;
            #pragma unroll
            for (int k = 0; k < 3; k++) { o0 += v0[s + k] * d0[k]; o1 += v1[s + k] * d1[k]; }
            hB[f0 * H1S + 1 + 4*p + s] = eluf(o0);
            hB[f1 * H1S + 1 + 4*p + s] = eluf(o1);
        }
    }

    // separable depthwise K=3 (no act)  (hB -> hA, laid out [f][t] at offset 0)
    float e0[3], e1[3];
    #pragma unroll
    for (int k = 0; k < 3; k++) { e0[k] = sdww[f0 * 3 + k]; e1[k] = sdww[f1 * 3 + k]; }
    for (int p = lane; p < 125; p += 32) {
        float v0[6], v1[6];
        #pragma unroll
        for (int q = 0; q < 6; q++) { v0[q] = hB[f0 * H1S + 4*p + q]; v1[q] = hB[f1 * H1S + 4*p + q]; }
        #pragma unroll
        for (int s = 0; s < 4; s++) {
            float o0 = 0.f, o1 = 0.f;
            #pragma unroll
            for (int k = 0; k < 3; k++) { o0 += v0[s + k] * e0[k]; o1 += v1[s + k] * e1[k]; }
            hA[f0 * H1S + 4*p + s] = o0;
            hA[f1 * H1S + 4*p + s] = o1;
        }
    }
    __syncthreads();  // pointwise reads all channels

    // pointwise 16->16 + BN3 + ELU + temporal mean
    float psc0 = bn3[f0] * rsqrtf(bn3[48 + f0] + 1e-5f);
    float psc1 = bn3[f1] * rsqrtf(bn3[48 + f1] + 1e-5f);
    float pb0  = bn3[16 + f0] - bn3[32 + f0] * psc0;
    float pb1  = bn3[16 + f1] - bn3[32 + f1] * psc1;
    float pw0[16], pw1[16];
    #pragma unroll
    for (int c = 0; c < 16; c++) { pw0[c] = spww[f0 * 16 + c] * psc0; pw1[c] = spww[f1 * 16 + c] * psc1; }
    float s0 = 0.f, s1 = 0.f;
    for (int p = lane; p < 125; p += 32) {
        float a0[4] = {pb0, pb0, pb0, pb0}, a1[4] = {pb1, pb1, pb1, pb1};
        #pragma unroll
        for (int c = 0; c < 16; c++) {
            const float4 v = *(const float4*)&hA[c * H1S + 4*p];
            a0[0] += v.x * pw0[c]; a0[1] += v.y * pw0[c]; a0[2] += v.z * pw0[c]; a0[3] += v.w * pw0[c];
            a1[0] += v.x * pw1[c]; a1[1] += v.y * pw1[c]; a1[2] += v.z * pw1[c]; a1[3] += v.w * pw1[c];
        }
        #pragma unroll
        for (int s = 0; s < 4; s++) { s0 += eluf(a0[s]); s1 += eluf(a1[s]); }
    }
    #pragma unroll
    for (int o = 16; o > 0; o >>= 1) {
        s0 += __shfl_xor_sync(0xffffffffu, s0, o);
        s1 += __shfl_xor_sync(0xffffffffu, s1, o);
    }
    if (lane == 0) {
        g_feats[seq * 16 + f0] = s0 * (1.f / 500.f);
        g_feats[seq * 16 + f1] = s1 * (1.f / 500.f);
    }
}

// ---------------------------------------------------------------------------
// K2: GAT layer 1 per batch sample (128 blocks x 256 thr)
// ---------------------------------------------------------------------------
__global__ __launch_bounds__(256) void k2_gat1(
    const float* __restrict__ w1g,  const float* __restrict__ asrc,
    const float* __restrict__ adst, const float* __restrict__ bias,
    const float* __restrict__ bng,  const float* __restrict__ skw)
{
    extern __shared__ float sm[];
    float* fs  = sm;              // 1024  feats[64][16]
    float* Ws  = fs + 1024;       // 2048  gat1_w [16][128]
    float* xls = Ws + 2048;       // 8448  xl, row stride 132, head stride 33
    float* ho  = xls + 8448;      // 8448  per-(i,h) out, stride 33
    float* sv  = ho + 8448;       // 256
    float* dv  = sv + 256;        // 256
    float* asr = dv + 256;        // 128
    float* ads = asr + 128;       // 128
    float* lM  = ads + 128;       // 4096
    float* skT = lM + 4096;       // 512   skip1_w transposed [c][f]
    float* vt  = skT + 512;       // 2048
    int tid = threadIdx.x;
    int b = blockIdx.x;

    for (int i = tid; i < 1024; i += 256) fs[i] = g_feats[b * 1024 + i];
    for (int i = tid; i < 2048; i += 256) Ws[i] = w1g[i];
    if (tid < 128) { asr[tid] = asrc[tid]; ads[tid] = adst[tid]; }
    for (int i = tid; i < 4096; i += 256) lM[i] = g_elogM[i];
    for (int i = tid; i < 512; i += 256) {
        int f = i >> 4, c = i & 15;                    // skw is [32][16]
        skT[c * 32 + f] = skw[i];
    }
    __syncthreads();

    for (int idx = tid; idx < 8192; idx += 256) {
        int j = idx >> 7, col = idx & 127, h = col >> 5, f = col & 31;
        float a = 0.f;
        #pragma unroll
        for (int c = 0; c < 16; c++) a += fs[j * 16 + c] * Ws[c * 128 + col];
        xls[j * 132 + h * 33 + f] = a;
    }
    __syncthreads();

    for (int idx = tid; idx < 512; idx += 256) {
        int sflag = idx >> 8, jh = idx & 255, j = jh >> 2, h = jh & 3;
        const float* av = sflag ? ads : asr;
        float a = 0.f;
        #pragma unroll
        for (int f = 0; f < 32; f++) a += xls[j * 132 + h * 33 + f] * av[h * 32 + f];
        if (sflag) dv[j * 4 + h] = a; else sv[j * 4 + h] = a;
    }
    __syncthreads();

    {
        int i = tid >> 2, h = tid & 3;
        float di = dv[i * 4 + h];
        float mx = -1e30f;
        for (int j = 0; j < 64; j++) {
            float e = lrelu(di + sv[j * 4 + h]) + lM[i * 64 + j];
            mx = fmaxf(mx, e);
        }
        float acc[32];
        #pragma unroll
        for (int f = 0; f < 32; f++) acc[f] = 0.f;
        float den = 0.f;
        for (int j = 0; j < 64; j++) {
            float e = lrelu(di + sv[j * 4 + h]) + lM[i * 64 + j];
            float wgt = expf(e - mx);
            den += wgt;
            const float* xr = &xls[j * 132 + h * 33];
            #pragma unroll
            for (int f = 0; f < 32; f++) acc[f] += wgt * xr[f];
        }
        float inv = 1.f / den;
        #pragma unroll
        for (int f = 0; f < 32; f++) ho[tid * 33 + f] = acc[f] * inv;
    }
    __syncthreads();

    for (int idx = tid; idx < 2048; idx += 256) {
        int i = idx >> 5, f = idx & 31;
        float o = 0.25f * (ho[(i*4+0)*33+f] + ho[(i*4+1)*33+f] + ho[(i*4+2)*33+f] + ho[(i*4+3)*33+f])
                  + bias[f];
        float sc = bng[f] * rsqrtf(bng[96 + f] + 1e-5f);
        o = (o - bng[64 + f]) * sc + bng[32 + f];
        float sk = 0.f;
        #pragma unroll
        for (int c = 0; c < 16; c++) sk += fs[i * 16 + c] * skT[c * 32 + f];
        float v = geluf(o + sk);
        g_h1[(b * 64 + i) * 32 + f] = v;
        vt[idx] = v;
    }
    __syncthreads();
    if (tid < 32) {
        float s = 0.f;
        for (int i = 0; i < 64; i++) s += vt[i * 32 + tid];
        g_ps1[b * 32 + tid] = s;
    }
}

// ---------------------------------------------------------------------------
// K4: SE-gate1 + GAT layer 2 per batch sample
// ---------------------------------------------------------------------------
__global__ __launch_bounds__(256) void k4_gat2(
    const float* __restrict__ w2g,  const float* __restrict__ asrc,
    const float* __restrict__ adst, const float* __restrict__ bias,
    const float* __restrict__ bng,  const float* __restrict__ se1a,
    const float* __restrict__ se1b)
{
    extern __shared__ float sm[];
    float* xin = sm;              // 2048  gated h1 [64][32]
    float* Ws  = xin + 2048;      // 4096  gat2_w [32][128]
    float* xls = Ws + 4096;       // 8448
    float* ho  = xls + 8448;      // 8448
    float* sv  = ho + 8448;       // 256
    float* dv  = sv + 256;        // 256
    float* asr = dv + 256;        // 128
    float* ads = asr + 128;       // 128
    float* lM  = ads + 128;       // 4096
    float* vt  = lM + 4096;       // 2048
    float* gate = vt + 2048;      // 72: m[32], t1[8], g[32]
    int tid = threadIdx.x;
    int b = blockIdx.x;

    // SE gate 1 (redundant per block, deterministic fixed-order sum)
    if (tid < 32) {
        float s = 0.f;
        for (int bb = 0; bb < 128; bb++) s += g_ps1[bb * 32 + tid];
        gate[tid] = s * (1.f / 8192.f);
    }
    __syncthreads();
    if (tid < 8) {
        float a = 0.f;
        #pragma unroll
        for (int c = 0; c < 32; c++) a += gate[c] * se1a[tid * 32 + c];
        gate[32 + tid] = fmaxf(a, 0.f);
    }
    __syncthreads();
    if (tid < 32) {
        float a = 0.f;
        #pragma unroll
        for (int r = 0; r < 8; r++) a += gate[32 + r] * se1b[tid * 8 + r];
        gate[40 + tid] = sigm(a);
    }
    for (int i = tid; i < 4096; i += 256) Ws[i] = w2g[i];
    if (tid < 128) { asr[tid] = asrc[tid]; ads[tid] = adst[tid]; }
    for (int i = tid; i < 4096; i += 256) lM[i] = g_elogM[i];
    __syncthreads();

    for (int idx = tid; idx < 2048; idx += 256) {
        int f = idx & 31;
        xin[idx] = g_h1[b * 2048 + idx] * gate[40 + f];
    }
    __syncthreads();

    for (int idx = tid; idx < 8192; idx += 256) {
        int j = idx >> 7, col = idx & 127, h = col >> 5, f = col & 31;
        float a = 0.f;
        #pragma unroll
        for (int c = 0; c < 32; c++) a += xin[j * 32 + c] * Ws[c * 128 + col];
        xls[j * 132 + h * 33 + f] = a;
    }
    __syncthreads();

    for (int idx = tid; idx < 512; idx += 256) {
        int sflag = idx >> 8, jh = idx & 255, j = jh >> 2, h = jh & 3;
        const float* av = sflag ? ads : asr;
        float a = 0.f;
        #pragma unroll
        for (int f = 0; f < 32; f++) a += xls[j * 132 + h * 33 + f] * av[h * 32 + f];
        if (sflag) dv[j * 4 + h] = a; else sv[j * 4 + h] = a;
    }
    __syncthreads();

    {
        int i = tid >> 2, h = tid & 3;
        float di = dv[i * 4 + h];
        float mx = -1e30f;
        for (int j = 0; j < 64; j++) {
            float e = lrelu(di + sv[j * 4 + h]) + lM[i * 64 + j];
            mx = fmaxf(mx, e);
        }
        float acc[32];
        #pragma unroll
        for (int f = 0; f < 32; f++) acc[f] = 0.f;
        float den = 0.f;
        for (int j = 0; j < 64; j++) {
            float e = lrelu(di + sv[j * 4 + h]) + lM[i * 64 + j];
            float wgt = expf(e - mx);
            den += wgt;
            const float* xr = &xls[j * 132 + h * 33];
            #pragma unroll
            for (int f = 0; f < 32; f++) acc[f] += wgt * xr[f];
        }
        float inv = 1.f / den;
        #pragma unroll
        for (int f = 0; f < 32; f++) ho[tid * 33 + f] = acc[f] * inv;
    }
    __syncthreads();

    for (int idx = tid; idx < 2048; idx += 256) {
        int i = idx >> 5, f = idx & 31;
        float o = 0.25f * (ho[(i*4+0)*33+f] + ho[(i*4+1)*33+f] + ho[(i*4+2)*33+f] + ho[(i*4+3)*33+f])
                  + bias[f];
        float sc = bng[f] * rsqrtf(bng[96 + f] + 1e-5f);
        o = (o - bng[64 + f]) * sc + bng[32 + f];
        float v = geluf(o + xin[i * 32 + f]);   // residual = gated h1
        g_h2[(b * 64 + i) * 32 + f] = v;
        vt[idx] = v;
    }
    __syncthreads();
    if (tid < 32) {
        float s = 0.f;
        for (int i = 0; i < 64; i++) s += vt[i * 32 + tid];
        g_ps2[b * 32 + tid] = s;
    }
}

// ---------------------------------------------------------------------------
// K6: SE-gate2 + node pooling + classifier (128 blocks x 32 thr)
// ---------------------------------------------------------------------------
__global__ void k6_out(const float* __restrict__ se2a, const float* __restrict__ se2b,
                       const float* __restrict__ clfw, const float* __restrict__ clfb,
                       float* __restrict__ out)
{
    __shared__ float m[32], t1[8];
    int f = threadIdx.x;
    int b = blockIdx.x;
    float s = 0.f;
    for (int bb = 0; bb < 128; bb++) s += g_ps2[bb * 32 + f];
    m[f] = s * (1.f / 8192.f);
    __syncwarp();
    if (f < 8) {
        float a = 0.f;
        #pragma unroll
        for (int c = 0; c < 32; c++) a += m[c] * se2a[f * 32 + c];
        t1[f] = fmaxf(a, 0.f);
    }
    __syncwarp();
    float a = 0.f;
    #pragma unroll
    for (int r = 0; r < 8; r++) a += t1[r] * se2b[f * 8 + r];
    float gg = sigm(a);

    float acc = 0.f;
    const float* hp = g_h2 + b * 2048;
    for (int i = 0; i < 64; i++) acc += hp[i * 32 + f];
    float pooled = acc * gg * (1.f / 64.f);
    float r0 = pooled * clfw[f];
    float r1 = pooled * clfw[32 + f];
    #pragma unroll
    for (int o = 16; o > 0; o >>= 1) {
        r0 += __shfl_xor_sync(0xffffffffu, r0, o);
        r1 += __shfl_xor_sync(0xffffffffu, r1, o);
    }
    if (f == 0) {
        out[b * 2 + 0] = r0 + clfb[0];
        out[b * 2 + 1] = r1 + clfb[1];
    }
}

// ---------------------------------------------------------------------------
extern "C" void kernel_launch(void* const* d_in, const int* in_sizes, int n_in,
                              void* d_out, int out_size)
{
    const float* x    = (const float*)d_in[0];
    const int*   ei   = (const int*)  d_in[1];
    const float* c1w  = (const float*)d_in[2];
    const float* bn1  = (const float*)d_in[3];
    const float* dww  = (const float*)d_in[4];
    const float* bn2  = (const float*)d_in[5];
    const float* sdww = (const float*)d_in[6];
    const float* spww = (const float*)d_in[7];
    const float* bn3  = (const float*)d_in[8];
    const float* nemb = (const float*)d_in[9];
    const float* g1w  = (const float*)d_in[10];
    const float* g1as = (const float*)d_in[11];
    const float* g1ad = (const float*)d_in[12];
    const float* g1b  = (const float*)d_in[13];
    const float* bng1 = (const float*)d_in[14];
    const float* sk1  = (const float*)d_in[15];
    const float* se1a = (const float*)d_in[16];
    const float* se1b = (const float*)d_in[17];
    const float* g2w  = (const float*)d_in[18];
    const float* g2as = (const float*)d_in[19];
    const float* g2ad = (const float*)d_in[20];
    const float* g2b  = (const float*)d_in[21];
    const float* bng2 = (const float*)d_in[22];
    const float* se2a = (const float*)d_in[23];
    const float* se2b = (const float*)d_in[24];
    const float* clfw = (const float*)d_in[25];
    const float* clfb = (const float*)d_in[26];
    float* out = (float*)d_out;

    const int SM1 = 16656 * 4;   // 66,624 B
    const int SM2 = 27392 * 4;   // 109,568 B
    const int SM4 = 30024 * 4;   // 120,096 B
    cudaFuncSetAttribute(k1_feat, cudaFuncAttributeMaxDynamicSharedMemorySize, SM1);
    cudaFuncSetAttribute(k2_gat1, cudaFuncAttributeMaxDynamicSharedMemorySize, SM2);
    cudaFuncSetAttribute(k4_gat2, cudaFuncAttributeMaxDynamicSharedMemorySize, SM4);

    k0_graph<<<1, 256>>>(nemb, ei);
    k1_feat<<<NSEQ, 256, SM1>>>(x, c1w, bn1, dww, bn2, sdww, spww, bn3);
    k2_gat1<<<128, 256, SM2>>>(g1w, g1as, g1ad, g1b, bng1, sk1);
    k4_gat2<<<128, 256, SM4>>>(g2w, g2as, g2ad, g2b, bng2, se1a, se1b);
    k6_out<<<128, 32>>>(se2a, se2b, clfw, clfb, out);
}

// round 2
// speedup vs baseline: 1.3169x; 1.3169x over previous
#include <cuda_runtime.h>
#include <math.h>

// ---------------------------------------------------------------------------
// Improved_DSTGAT_Attn_Adaptive — R2
//  k1: fast ELU (__expf) + f32x2 packed FFMA (channel pairs), weights in smem
//  k2/k4: 512 thr, single-pass softmax, reg e-cache, __expf, float4 xl loads
// ---------------------------------------------------------------------------

#define NSEQ 8192
#define TLEN 500
#define H1S  504
typedef unsigned long long ull;

__device__ float g_feats[NSEQ * 16];
__device__ float g_h1[NSEQ * 32];
__device__ float g_h2[NSEQ * 32];
__device__ float g_elogM[64 * 64];
__device__ float g_ps1[128 * 32];
__device__ float g_ps2[128 * 32];

__device__ __forceinline__ float elu1(float x) {
    float e = __expf(x) - 1.f;
    return x > 0.f ? x : e;
}
__device__ __forceinline__ float geluf(float x) { return 0.5f * x * (1.f + erff(x * 0.70710678118654752f)); }
__device__ __forceinline__ float sigm(float x)  { return 1.f / (1.f + __expf(-x)); }

__device__ __forceinline__ ull pk(float lo, float hi) {
    ull r; asm("mov.b64 %0, {%1,%2};" : "=l"(r) : "f"(lo), "f"(hi)); return r;
}
__device__ __forceinline__ float2 upk(ull v) {
    float2 r; asm("mov.b64 {%0,%1}, %2;" : "=f"(r.x), "=f"(r.y) : "l"(v)); return r;
}
__device__ __forceinline__ ull dup2(float x) {
    ull r; asm("mov.b64 %0, {%1,%1};" : "=l"(r) : "f"(x)); return r;
}
__device__ __forceinline__ ull f2fma(ull a, ull b, ull c) {
    ull d; asm("fma.rn.f32x2 %0, %1, %2, %3;" : "=l"(d) : "l"(a), "l"(b), "l"(c)); return d;
}

// ---------------------------------------------------------------------------
// K0: adjacency / multiplicity matrix -> log-mask
// ---------------------------------------------------------------------------
__global__ void k0_graph(const float* __restrict__ E, const int* __restrict__ ei)
{
    __shared__ float Es[64 * 16];
    __shared__ float As[64 * 65];
    __shared__ float den[64];
    __shared__ int   Ms[64 * 64];
    int tid = threadIdx.x;
    for (int i = tid; i < 1024; i += 256) Es[i] = E[i];
    for (int i = tid; i < 4096; i += 256) Ms[i] = 0;
    __syncthreads();
    for (int idx = tid; idx < 4096; idx += 256) {
        int i = idx >> 6, j = idx & 63;
        float a = 0.f;
        #pragma unroll
        for (int c = 0; c < 16; c++) a += Es[i * 16 + c] * Es[j * 16 + c];
        As[i * 65 + j] = a > 0.f ? a : 0.f;
    }
    __syncthreads();
    for (int i = tid; i < 64; i += 256) {
        float s = 0.f;
        for (int j = 0; j < 64; j++) s += As[i * 65 + j];
        den[i] = s + 1e-6f;
    }
    __syncthreads();
    if (tid < 256) atomicAdd(&Ms[ei[tid] * 64 + ei[256 + tid]], 1);
    __syncthreads();
    for (int idx = tid; idx < 4096; idx += 256) {
        int i = idx >> 6, j = idx & 63;
        float dyn = (As[i * 65 + j] / den[i] > 0.1f) ? 1.f : 0.f;
        float Mv  = (i == j) ? 1.f : ((float)Ms[idx] + dyn);
        g_elogM[idx] = (Mv > 0.f) ? logf(Mv) : -1e30f;
    }
}

// ---------------------------------------------------------------------------
// K1: fused feature extractor. One CTA per sequence, 8 warps, warp owns 2 ch
// packed into f32x2 lanes. Folded packed weights staged in smem.
// ---------------------------------------------------------------------------
__global__ __launch_bounds__(256) void k1_feat(
    const float* __restrict__ x,
    const float* __restrict__ c1w,  const float* __restrict__ bn1,
    const float* __restrict__ dww,  const float* __restrict__ bn2,
    const float* __restrict__ sdww, const float* __restrict__ spww,
    const float* __restrict__ bn3)
{
    extern __shared__ float sm[];
    ull* c1pS  = (ull*)sm;          // 200
    ull* c1bS  = c1pS + 200;        // 8
    ull* dwpS  = c1bS + 8;          // 24
    ull* dwbS  = dwpS + 24;         // 8
    ull* sdpS  = dwbS + 8;          // 24
    ull* pw0dS = sdpS + 24;         // 128
    ull* pw1dS = pw0dS + 128;       // 128
    float* xs = sm + 1040;          // 528
    float* hA = xs + 528;           // 16*504
    float* hB = hA + 16 * H1S;      // 16*504

    int tid = threadIdx.x, warp = tid >> 5, lane = tid & 31;
    int seq = blockIdx.x;
    const float* xp = x + (size_t)seq * TLEN;

    for (int i = tid; i < 528; i += 256) {
        int t = i - 12;
        xs[i] = (t >= 0 && t < TLEN) ? xp[t] : 0.f;
    }
    if (tid < 16) {
        hA[tid * H1S] = 0.f; hA[tid * H1S + 501] = 0.f;
        hB[tid * H1S] = 0.f; hB[tid * H1S + 501] = 0.f;
    }

    int f0 = warp * 2, f1 = f0 + 1;

    // fold all BN params (every lane computes uniform per-warp scalars)
    float sc0 = bn1[f0] * rsqrtf(bn1[48 + f0] + 1e-5f);
    float sc1 = bn1[f1] * rsqrtf(bn1[48 + f1] + 1e-5f);
    float b0  = bn1[16 + f0] - bn1[32 + f0] * sc0;
    float b1  = bn1[16 + f1] - bn1[32 + f1] * sc1;
    float dsc0 = bn2[f0] * rsqrtf(bn2[48 + f0] + 1e-5f);
    float dsc1 = bn2[f1] * rsqrtf(bn2[48 + f1] + 1e-5f);
    float db0  = bn2[16 + f0] - bn2[32 + f0] * dsc0;
    float db1  = bn2[16 + f1] - bn2[32 + f1] * dsc1;
    float psc0 = bn3[f0] * rsqrtf(bn3[48 + f0] + 1e-5f);
    float psc1 = bn3[f1] * rsqrtf(bn3[48 + f1] + 1e-5f);
    float pb0  = bn3[16 + f0] - bn3[32 + f0] * psc0;
    float pb1  = bn3[16 + f1] - bn3[32 + f1] * psc1;

    if (lane < 25)      c1pS[warp * 25 + lane] = pk(c1w[f0 * 25 + lane] * sc0, c1w[f1 * 25 + lane] * sc1);
    else if (lane == 25) c1bS[warp] = pk(b0, b1);
    else if (lane == 26) dwbS[warp] = pk(db0, db1);
    else if (lane < 30) { int k = lane - 27; dwpS[warp * 3 + k] = pk(dww[f0 * 3 + k] * dsc0, dww[f1 * 3 + k] * dsc1); }
    if (lane < 3)  sdpS[warp * 3 + lane] = pk(sdww[f0 * 3 + lane], sdww[f1 * 3 + lane]);
    if (lane < 16) {
        pw0dS[warp * 16 + lane] = dup2(spww[f0 * 16 + lane] * psc0);
        pw1dS[warp * 16 + lane] = dup2(spww[f1 * 16 + lane] * psc1);
    }
    __syncthreads();

    // ---- conv1 K=25 + BN + ELU ----
    {
        ull cb = c1bS[warp];
        for (int p = lane; p < 125; p += 32) {
            const float4* xq = ((const float4*)xs) + p;
            float xw[28];
            #pragma unroll
            for (int q = 0; q < 7; q++) {
                float4 v = xq[q];
                xw[4*q] = v.x; xw[4*q+1] = v.y; xw[4*q+2] = v.z; xw[4*q+3] = v.w;
            }
            ull a0 = cb, a1 = cb, a2 = cb, a3 = cb;
            ull r0 = dup2(xw[0]), r1 = dup2(xw[1]), r2 = dup2(xw[2]);
            #pragma unroll
            for (int k = 0; k < 25; k++) {
                ull r3 = dup2(xw[k + 3]);
                ull wk = c1pS[warp * 25 + k];
                a0 = f2fma(r0, wk, a0);
                a1 = f2fma(r1, wk, a1);
                a2 = f2fma(r2, wk, a2);
                a3 = f2fma(r3, wk, a3);
                r0 = r1; r1 = r2; r2 = r3;
            }
            float2 v0 = upk(a0), v1 = upk(a1), v2 = upk(a2), v3 = upk(a3);
            int ba = f0 * H1S + 1 + 4 * p, bb = f1 * H1S + 1 + 4 * p;
            hA[ba+0] = elu1(v0.x); hA[ba+1] = elu1(v1.x); hA[ba+2] = elu1(v2.x); hA[ba+3] = elu1(v3.x);
            hA[bb+0] = elu1(v0.y); hA[bb+1] = elu1(v1.y); hA[bb+2] = elu1(v2.y); hA[bb+3] = elu1(v3.y);
        }
    }
    __syncwarp();

    // ---- depthwise K=3 + BN + ELU (hA -> hB) ----
    {
        ull db = dwbS[warp];
        ull d0 = dwpS[warp * 3 + 0], d1 = dwpS[warp * 3 + 1], d2 = dwpS[warp * 3 + 2];
        for (int p = lane; p < 125; p += 32) {
            ull xp6[6];
            #pragma unroll
            for (int q = 0; q < 6; q++)
                xp6[q] = pk(hA[f0 * H1S + 4*p + q], hA[f1 * H1S + 4*p + q]);
            #pragma unroll
            for (int s = 0; s < 4; s++) {
                ull a = db;
                a = f2fma(xp6[s],     d0, a);
                a = f2fma(xp6[s + 1], d1, a);
                a = f2fma(xp6[s + 2], d2, a);
                float2 v = upk(a);
                hB[f0 * H1S + 1 + 4*p + s] = elu1(v.x);
                hB[f1 * H1S + 1 + 4*p + s] = elu1(v.y);
            }
        }
    }
    __syncwarp();

    // ---- separable depthwise K=3 (no act) (hB -> hA at offset 0) ----
    {
        ull e0 = sdpS[warp * 3 + 0], e1 = sdpS[warp * 3 + 1], e2 = sdpS[warp * 3 + 2];
        const ull z = 0;
        for (int p = lane; p < 125; p += 32) {
            ull xp6[6];
            #pragma unroll
            for (int q = 0; q < 6; q++)
                xp6[q] = pk(hB[f0 * H1S + 4*p + q], hB[f1 * H1S + 4*p + q]);
            #pragma unroll
            for (int s = 0; s < 4; s++) {
                ull a = z;
                a = f2fma(xp6[s],     e0, a);
                a = f2fma(xp6[s + 1], e1, a);
                a = f2fma(xp6[s + 2], e2, a);
                float2 v = upk(a);
                hA[f0 * H1S + 4*p + s] = v.x;
                hA[f1 * H1S + 4*p + s] = v.y;
            }
        }
    }
    __syncthreads();

    // ---- pointwise 16->16 + BN + ELU + temporal mean ----
    {
        float s0 = 0.f, s1 = 0.f;
        for (int p = lane; p < 125; p += 32) {
            ull a01_0 = dup2(pb0), a23_0 = dup2(pb0);
            ull a01_1 = dup2(pb1), a23_1 = dup2(pb1);
            #pragma unroll
            for (int c = 0; c < 16; c++) {
                float4 v = *(const float4*)&hA[c * H1S + 4*p];
                ull x01 = pk(v.x, v.y), x23 = pk(v.z, v.w);
                ull w0d = pw0dS[warp * 16 + c], w1d = pw1dS[warp * 16 + c];
                a01_0 = f2fma(x01, w0d, a01_0);
                a23_0 = f2fma(x23, w0d, a23_0);
                a01_1 = f2fma(x01, w1d, a01_1);
                a23_1 = f2fma(x23, w1d, a23_1);
            }
            float2 u;
            u = upk(a01_0); s0 += elu1(u.x) + elu1(u.y);
            u = upk(a23_0); s0 += elu1(u.x) + elu1(u.y);
            u = upk(a01_1); s1 += elu1(u.x) + elu1(u.y);
            u = upk(a23_1); s1 += elu1(u.x) + elu1(u.y);
        }
        #pragma unroll
        for (int o = 16; o > 0; o >>= 1) {
            s0 += __shfl_xor_sync(0xffffffffu, s0, o);
            s1 += __shfl_xor_sync(0xffffffffu, s1, o);
        }
        if (lane == 0) {
            g_feats[seq * 16 + f0] = s0 * (1.f / 500.f);
            g_feats[seq * 16 + f1] = s1 * (1.f / 500.f);
        }
    }
}

// ---------------------------------------------------------------------------
// shared GAT attention core: 512 threads -> 256 (i,h) pairs x 2 j-halves
// xls layout: j*148 + h*36 + f (float4-aligned)
// ---------------------------------------------------------------------------
__device__ __forceinline__ void gat_attn(const float* xls, const float* sv, const float* dv,
                                         const float* lM, float* ho, int tid)
{
    int ih = tid >> 1, half = tid & 1;
    int i = ih >> 2, h = ih & 3;
    int j0 = half << 5;
    float di = dv[i * 4 + h];
    float e[32];
    float mx = -1e30f;
    #pragma unroll
    for (int jj = 0; jj < 32; jj++) {
        float t = di + sv[(j0 + jj) * 4 + h];
        e[jj] = (t > 0.f ? t : 0.2f * t) + lM[i * 64 + j0 + jj];
        mx = fmaxf(mx, e[jj]);
    }
    mx = fmaxf(mx, __shfl_xor_sync(0xffffffffu, mx, 1));
    float den = 0.f;
    float acc[32];
    #pragma unroll
    for (int f = 0; f < 32; f++) acc[f] = 0.f;
    #pragma unroll
    for (int jj = 0; jj < 32; jj++) {
        float wgt = __expf(e[jj] - mx);
        den += wgt;
        const float* xr = &xls[(j0 + jj) * 148 + h * 36];
        #pragma unroll
        for (int f = 0; f < 32; f += 4) {
            float4 v = *(const float4*)&xr[f];
            acc[f+0] += wgt * v.x; acc[f+1] += wgt * v.y;
            acc[f+2] += wgt * v.z; acc[f+3] += wgt * v.w;
        }
    }
    den += __shfl_xor_sync(0xffffffffu, den, 1);
    #pragma unroll
    for (int f = 0; f < 32; f++) acc[f] += __shfl_xor_sync(0xffffffffu, acc[f], 1);
    float inv = 1.f / den;
    if (half == 0) {
        #pragma unroll
        for (int f = 0; f < 16; f++) ho[ih * 33 + f] = acc[f] * inv;
    } else {
        #pragma unroll
        for (int f = 16; f < 32; f++) ho[ih * 33 + f] = acc[f] * inv;
    }
}

// ---------------------------------------------------------------------------
// K2: GAT layer 1 (128 blocks x 512 thr)
// ---------------------------------------------------------------------------
__global__ __launch_bounds__(512) void k2_gat1(
    const float* __restrict__ w1g,  const float* __restrict__ asrc,
    const float* __restrict__ adst, const float* __restrict__ bias,
    const float* __restrict__ bng,  const float* __restrict__ skw)
{
    extern __shared__ float sm[];
    float* fs  = sm;              // 1024
    float* Ws  = fs + 1024;       // 2048
    float* xls = Ws + 2048;       // 9472  (64 x 148)
    float* ho  = xls + 9472;      // 8448  (256 x 33)
    float* sv  = ho + 8448;       // 256
    float* dv  = sv + 256;        // 256
    float* asr = dv + 256;        // 128
    float* ads = asr + 128;       // 128
    float* lM  = ads + 128;       // 4096
    float* skT = lM + 4096;       // 512
    float* vt  = skT + 512;       // 2048
    int tid = threadIdx.x;
    int b = blockIdx.x;

    for (int i = tid; i < 1024; i += 512) fs[i] = g_feats[b * 1024 + i];
    for (int i = tid; i < 2048; i += 512) Ws[i] = w1g[i];
    if (tid < 128) { asr[tid] = asrc[tid]; ads[tid] = adst[tid]; }
    for (int i = tid; i < 4096; i += 512) lM[i] = g_elogM[i];
    if (tid < 512) {
        int f = tid >> 4, c = tid & 15;     // skw [32][16]
        skT[c * 32 + f] = skw[tid];
    }
    __syncthreads();

    for (int idx = tid; idx < 8192; idx += 512) {
        int j = idx >> 7, col = idx & 127, h = col >> 5, f = col & 31;
        float a = 0.f;
        #pragma unroll
        for (int c = 0; c < 16; c++) a += fs[j * 16 + c] * Ws[c * 128 + col];
        xls[j * 148 + h * 36 + f] = a;
    }
    __syncthreads();

    {
        int sflag = tid >> 8, jh = tid & 255, j = jh >> 2, h = jh & 3;
        const float* av = sflag ? ads : asr;
        float a = 0.f;
        #pragma unroll
        for (int f = 0; f < 32; f++) a += xls[j * 148 + h * 36 + f] * av[h * 32 + f];
        if (sflag) dv[j * 4 + h] = a; else sv[j * 4 + h] = a;
    }
    __syncthreads();

    gat_attn(xls, sv, dv, lM, ho, tid);
    __syncthreads();

    for (int idx = tid; idx < 2048; idx += 512) {
        int i = idx >> 5, f = idx & 31;
        float o = 0.25f * (ho[(i*4+0)*33+f] + ho[(i*4+1)*33+f] + ho[(i*4+2)*33+f] + ho[(i*4+3)*33+f])
                  + bias[f];
        float sc = bng[f] * rsqrtf(bng[96 + f] + 1e-5f);
        o = (o - bng[64 + f]) * sc + bng[32 + f];
        float sk = 0.f;
        #pragma unroll
        for (int c = 0; c < 16; c++) sk += fs[i * 16 + c] * skT[c * 32 + f];
        float v = geluf(o + sk);
        g_h1[(b * 64 + i) * 32 + f] = v;
        vt[idx] = v;
    }
    __syncthreads();
    if (tid < 32) {
        float s = 0.f;
        for (int i = 0; i < 64; i++) s += vt[i * 32 + tid];
        g_ps1[b * 32 + tid] = s;
    }
}

// ---------------------------------------------------------------------------
// K4: SE-gate1 + GAT layer 2 (128 blocks x 512 thr)
// ---------------------------------------------------------------------------
__global__ __launch_bounds__(512) void k4_gat2(
    const float* __restrict__ w2g,  const float* __restrict__ asrc,
    const float* __restrict__ adst, const float* __restrict__ bias,
    const float* __restrict__ bng,  const float* __restrict__ se1a,
    const float* __restrict__ se1b)
{
    extern __shared__ float sm[];
    float* xin = sm;              // 2048
    float* Ws  = xin + 2048;      // 4096
    float* xls = Ws + 4096;       // 9472
    float* ho  = xls + 9472;      // 8448
    float* sv  = ho + 8448;       // 256
    float* dv  = sv + 256;        // 256
    float* asr = dv + 256;        // 128
    float* ads = asr + 128;       // 128
    float* lM  = ads + 128;       // 4096
    float* vt  = lM + 4096;       // 2048
    float* gate = vt + 2048;      // 72
    int tid = threadIdx.x;
    int b = blockIdx.x;

    if (tid < 32) {
        float s = 0.f;
        for (int bb = 0; bb < 128; bb++) s += g_ps1[bb * 32 + tid];
        gate[tid] = s * (1.f / 8192.f);
    }
    __syncthreads();
    if (tid < 8) {
        float a = 0.f;
        #pragma unroll
        for (int c = 0; c < 32; c++) a += gate[c] * se1a[tid * 32 + c];
        gate[32 + tid] = fmaxf(a, 0.f);
    }
    __syncthreads();
    if (tid < 32) {
        float a = 0.f;
        #pragma unroll
        for (int r = 0; r < 8; r++) a += gate[32 + r] * se1b[tid * 8 + r];
        gate[40 + tid] = sigm(a);
    }
    for (int i = tid; i < 4096; i += 512) Ws[i] = w2g[i];
    if (tid < 128) { asr[tid] = asrc[tid]; ads[tid] = adst[tid]; }
    for (int i = tid; i < 4096; i += 512) lM[i] = g_elogM[i];
    __syncthreads();

    for (int idx = tid; idx < 2048; idx += 512) {
        int f = idx & 31;
        xin[idx] = g_h1[b * 2048 + idx] * gate[40 + f];
    }
    __syncthreads();

    for (int idx = tid; idx < 8192; idx += 512) {
        int j = idx >> 7, col = idx & 127, h = col >> 5, f = col & 31;
        float a = 0.f;
        #pragma unroll
        for (int c = 0; c < 32; c++) a += xin[j * 32 + c] * Ws[c * 128 + col];
        xls[j * 148 + h * 36 + f] = a;
    }
    __syncthreads();

    {
        int sflag = tid >> 8, jh = tid & 255, j = jh >> 2, h = jh & 3;
        const float* av = sflag ? ads : asr;
        float a = 0.f;
        #pragma unroll
        for (int f = 0; f < 32; f++) a += xls[j * 148 + h * 36 + f] * av[h * 32 + f];
        if (sflag) dv[j * 4 + h] = a; else sv[j * 4 + h] = a;
    }
    __syncthreads();

    gat_attn(xls, sv, dv, lM, ho, tid);
    __syncthreads();

    for (int idx = tid; idx < 2048; idx += 512) {
        int i = idx >> 5, f = idx & 31;
        float o = 0.25f * (ho[(i*4+0)*33+f] + ho[(i*4+1)*33+f] + ho[(i*4+2)*33+f] + ho[(i*4+3)*33+f])
                  + bias[f];
        float sc = bng[f] * rsqrtf(bng[96 + f] + 1e-5f);
        o = (o - bng[64 + f]) * sc + bng[32 + f];
        float v = geluf(o + xin[idx]);
        g_h2[(b * 64 + i) * 32 + f] = v;
        vt[idx] = v;
    }
    __syncthreads();
    if (tid < 32) {
        float s = 0.f;
        for (int i = 0; i < 64; i++) s += vt[i * 32 + tid];
        g_ps2[b * 32 + tid] = s;
    }
}

// ---------------------------------------------------------------------------
// K6: SE-gate2 + node pooling + classifier
// ---------------------------------------------------------------------------
__global__ void k6_out(const float* __restrict__ se2a, const float* __restrict__ se2b,
                       const float* __restrict__ clfw, const float* __restrict__ clfb,
                       float* __restrict__ out)
{
    __shared__ float m[32], t1[8];
    int f = threadIdx.x;
    int b = blockIdx.x;
    float s = 0.f;
    for (int bb = 0; bb < 128; bb++) s += g_ps2[bb * 32 + f];
    m[f] = s * (1.f / 8192.f);
    __syncwarp();
    if (f < 8) {
        float a = 0.f;
        #pragma unroll
        for (int c = 0; c < 32; c++) a += m[c] * se2a[f * 32 + c];
        t1[f] = fmaxf(a, 0.f);
    }
    __syncwarp();
    float a = 0.f;
    #pragma unroll
    for (int r = 0; r < 8; r++) a += t1[r] * se2b[f * 8 + r];
    float gg = sigm(a);

    float acc = 0.f;
    const float* hp = g_h2 + b * 2048;
    for (int i = 0; i < 64; i++) acc += hp[i * 32 + f];
    float pooled = acc * gg * (1.f / 64.f);
    float r0 = pooled * clfw[f];
    float r1 = pooled * clfw[32 + f];
    #pragma unroll
    for (int o = 16; o > 0; o >>= 1) {
        r0 += __shfl_xor_sync(0xffffffffu, r0, o);
        r1 += __shfl_xor_sync(0xffffffffu, r1, o);
    }
    if (f == 0) {
        out[b * 2 + 0] = r0 + clfb[0];
        out[b * 2 + 1] = r1 + clfb[1];
    }
}

// ---------------------------------------------------------------------------
extern "C" void kernel_launch(void* const* d_in, const int* in_sizes, int n_in,
                              void* d_out, int out_size)
{
    const float* x    = (const float*)d_in[0];
    const int*   ei   = (const int*)  d_in[1];
    const float* c1w  = (const float*)d_in[2];
    const float* bn1  = (const float*)d_in[3];
    const float* dww  = (const float*)d_in[4];
    const float* bn2  = (const float*)d_in[5];
    const float* sdww = (const float*)d_in[6];
    const float* spww = (const float*)d_in[7];
    const float* bn3  = (const float*)d_in[8];
    const float* nemb = (const float*)d_in[9];
    const float* g1w  = (const float*)d_in[10];
    const float* g1as = (const float*)d_in[11];
    const float* g1ad = (const float*)d_in[12];
    const float* g1b  = (const float*)d_in[13];
    const float* bng1 = (const float*)d_in[14];
    const float* sk1  = (const float*)d_in[15];
    const float* se1a = (const float*)d_in[16];
    const float* se1b = (const float*)d_in[17];
    const float* g2w  = (const float*)d_in[18];
    const float* g2as = (const float*)d_in[19];
    const float* g2ad = (const float*)d_in[20];
    const float* g2b  = (const float*)d_in[21];
    const float* bng2 = (const float*)d_in[22];
    const float* se2a = (const float*)d_in[23];
    const float* se2b = (const float*)d_in[24];
    const float* clfw = (const float*)d_in[25];
    const float* clfb = (const float*)d_in[26];
    float* out = (float*)d_out;

    const int SM1 = 17696 * 4;   // 70,784 B
    const int SM2 = 28416 * 4;   // 113,664 B
    const int SM4 = 31048 * 4;   // 124,192 B
    cudaFuncSetAttribute(k1_feat, cudaFuncAttributeMaxDynamicSharedMemorySize, SM1);
    cudaFuncSetAttribute(k2_gat1, cudaFuncAttributeMaxDynamicSharedMemorySize, SM2);
    cudaFuncSetAttribute(k4_gat2, cudaFuncAttributeMaxDynamicSharedMemorySize, SM4);

    k0_graph<<<1, 256>>>(nemb, ei);
    k1_feat<<<NSEQ, 256, SM1>>>(x, c1w, bn1, dww, bn2, sdww, spww, bn3);
    k2_gat1<<<128, 512, SM2>>>(g1w, g1as, g1ad, g1b, bng1, sk1);
    k4_gat2<<<128, 512, SM4>>>(g2w, g2as, g2ad, g2b, bng2, se1a, se1b);
    k6_out<<<128, 32>>>(se2a, se2b, clfw, clfb, out);
}

// round 3
// speedup vs baseline: 1.4791x; 1.1232x over previous
#include <cuda_runtime.h>
#include <math.h>

// ---------------------------------------------------------------------------
// Improved_DSTGAT_Attn_Adaptive — R3
//  k1: fused dw+sdw (register chain), aligned STS.128/LDS.128, 3 CTAs/SM
//  k2/k4: two-pass attention (alpha matrix + 4x4-tiled aggregation matmul)
// ---------------------------------------------------------------------------

#define NSEQ 8192
#define TLEN 500
#define HS   512   // padded channel stride in k1 smem
typedef unsigned long long ull;

__device__ float g_feats[NSEQ * 16];
__device__ float g_h1[NSEQ * 32];
__device__ float g_h2[NSEQ * 32];
__device__ float g_elogM[64 * 64];
__device__ float g_ps1[128 * 32];
__device__ float g_ps2[128 * 32];

__device__ __forceinline__ float elu1(float x) {
    float e = __expf(x) - 1.f;
    return x > 0.f ? x : e;
}
__device__ __forceinline__ float geluf(float x) { return 0.5f * x * (1.f + erff(x * 0.70710678118654752f)); }
__device__ __forceinline__ float sigm(float x)  { return 1.f / (1.f + __expf(-x)); }

__device__ __forceinline__ ull pk(float lo, float hi) {
    ull r; asm("mov.b64 %0, {%1,%2};" : "=l"(r) : "f"(lo), "f"(hi)); return r;
}
__device__ __forceinline__ float2 upk(ull v) {
    float2 r; asm("mov.b64 {%0,%1}, %2;" : "=f"(r.x), "=f"(r.y) : "l"(v)); return r;
}
__device__ __forceinline__ ull dup2(float x) {
    ull r; asm("mov.b64 %0, {%1,%1};" : "=l"(r) : "f"(x)); return r;
}
__device__ __forceinline__ ull f2fma(ull a, ull b, ull c) {
    ull d; asm("fma.rn.f32x2 %0, %1, %2, %3;" : "=l"(d) : "l"(a), "l"(b), "l"(c)); return d;
}
__device__ __forceinline__ void fma4(float4& a, float s, const float4& v) {
    a.x += s * v.x; a.y += s * v.y; a.z += s * v.z; a.w += s * v.w;
}

// ---------------------------------------------------------------------------
// K0: adjacency / multiplicity matrix -> log-mask
// ---------------------------------------------------------------------------
__global__ void k0_graph(const float* __restrict__ E, const int* __restrict__ ei)
{
    __shared__ float Es[64 * 16];
    __shared__ float As[64 * 65];
    __shared__ float den[64];
    __shared__ int   Ms[64 * 64];
    int tid = threadIdx.x;
    for (int i = tid; i < 1024; i += 256) Es[i] = E[i];
    for (int i = tid; i < 4096; i += 256) Ms[i] = 0;
    __syncthreads();
    for (int idx = tid; idx < 4096; idx += 256) {
        int i = idx >> 6, j = idx & 63;
        float a = 0.f;
        #pragma unroll
        for (int c = 0; c < 16; c++) a += Es[i * 16 + c] * Es[j * 16 + c];
        As[i * 65 + j] = a > 0.f ? a : 0.f;
    }
    __syncthreads();
    for (int i = tid; i < 64; i += 256) {
        float s = 0.f;
        for (int j = 0; j < 64; j++) s += As[i * 65 + j];
        den[i] = s + 1e-6f;
    }
    __syncthreads();
    if (tid < 256) atomicAdd(&Ms[ei[tid] * 64 + ei[256 + tid]], 1);
    __syncthreads();
    for (int idx = tid; idx < 4096; idx += 256) {
        int i = idx >> 6, j = idx & 63;
        float dyn = (As[i * 65 + j] / den[i] > 0.1f) ? 1.f : 0.f;
        float Mv  = (i == j) ? 1.f : ((float)Ms[idx] + dyn);
        g_elogM[idx] = (Mv > 0.f) ? logf(Mv) : -1e30f;
    }
}

// ---------------------------------------------------------------------------
// K1: fused feature extractor. One CTA per sequence, 8 warps, warp owns 2 ch.
// hA[ch][tau], tau = t+4 (conv1 output); hB[ch][t] (sdw output).
// ---------------------------------------------------------------------------
__global__ __launch_bounds__(256, 3) void k1_feat(
    const float* __restrict__ x,
    const float* __restrict__ c1w,  const float* __restrict__ bn1,
    const float* __restrict__ dww,  const float* __restrict__ bn2,
    const float* __restrict__ sdww, const float* __restrict__ spww,
    const float* __restrict__ bn3)
{
    extern __shared__ float sm[];
    ull* c1pS  = (ull*)sm;          // 200
    ull* c1bS  = c1pS + 200;        // 8
    ull* dwpS  = c1bS + 8;          // 24
    ull* dwbS  = dwpS + 24;         // 8
    ull* sdpS  = dwbS + 8;          // 24
    ull* pw0dS = sdpS + 24;         // 128
    ull* pw1dS = pw0dS + 128;       // 128   -> 520 ull = 1040 floats
    float* xs = sm + 1040;          // 528
    float* hA = xs + 528;           // 16*512
    float* hB = hA + 16 * HS;       // 16*512
    // total = 1040+528+8192+8192 = 17952 floats

    int tid = threadIdx.x, warp = tid >> 5, lane = tid & 31;
    int seq = blockIdx.x;
    const float* xp = x + (size_t)seq * TLEN;

    for (int i = tid; i < 528; i += 256) {
        int t = i - 12;
        xs[i] = (t >= 0 && t < TLEN) ? xp[t] : 0.f;
    }
    if (tid < 16) {  // zero hA pads: tau 0..3 and 504..511
        float4 z = {0.f, 0.f, 0.f, 0.f};
        *(float4*)&hA[tid * HS]       = z;
        *(float4*)&hA[tid * HS + 504] = z;
        *(float4*)&hA[tid * HS + 508] = z;
    }

    int f0 = warp * 2, f1 = f0 + 1;

    // fold all BN params (uniform per warp)
    float sc0 = bn1[f0] * rsqrtf(bn1[48 + f0] + 1e-5f);
    float sc1 = bn1[f1] * rsqrtf(bn1[48 + f1] + 1e-5f);
    float b0  = bn1[16 + f0] - bn1[32 + f0] * sc0;
    float b1  = bn1[16 + f1] - bn1[32 + f1] * sc1;
    float dsc0 = bn2[f0] * rsqrtf(bn2[48 + f0] + 1e-5f);
    float dsc1 = bn2[f1] * rsqrtf(bn2[48 + f1] + 1e-5f);
    float db0  = bn2[16 + f0] - bn2[32 + f0] * dsc0;
    float db1  = bn2[16 + f1] - bn2[32 + f1] * dsc1;
    float psc0 = bn3[f0] * rsqrtf(bn3[48 + f0] + 1e-5f);
    float psc1 = bn3[f1] * rsqrtf(bn3[48 + f1] + 1e-5f);
    float pb0  = bn3[16 + f0] - bn3[32 + f0] * psc0;
    float pb1  = bn3[16 + f1] - bn3[32 + f1] * psc1;

    if (lane < 25)       c1pS[warp * 25 + lane] = pk(c1w[f0 * 25 + lane] * sc0, c1w[f1 * 25 + lane] * sc1);
    else if (lane == 25) c1bS[warp] = pk(b0, b1);
    else if (lane == 26) dwbS[warp] = pk(db0, db1);
    else if (lane < 30) { int k = lane - 27; dwpS[warp * 3 + k] = pk(dww[f0 * 3 + k] * dsc0, dww[f1 * 3 + k] * dsc1); }
    if (lane < 3)  sdpS[warp * 3 + lane] = pk(sdww[f0 * 3 + lane], sdww[f1 * 3 + lane]);
    if (lane < 16) {
        pw0dS[warp * 16 + lane] = dup2(spww[f0 * 16 + lane] * psc0);
        pw1dS[warp * 16 + lane] = dup2(spww[f1 * 16 + lane] * psc1);
    }
    __syncthreads();

    // ---- conv1 K=25 + BN + ELU -> hA[ch][t+4] ----
    {
        ull cb = c1bS[warp];
        for (int p = lane; p < 125; p += 32) {
            const float4* xq = ((const float4*)xs) + p;
            float xw[28];
            #pragma unroll
            for (int q = 0; q < 7; q++) {
                float4 v = xq[q];
                xw[4*q] = v.x; xw[4*q+1] = v.y; xw[4*q+2] = v.z; xw[4*q+3] = v.w;
            }
            ull a0 = cb, a1 = cb, a2 = cb, a3 = cb;
            ull r0 = dup2(xw[0]), r1 = dup2(xw[1]), r2 = dup2(xw[2]);
            #pragma unroll
            for (int k = 0; k < 25; k++) {
                ull r3 = dup2(xw[k + 3]);
                ull wk = c1pS[warp * 25 + k];
                a0 = f2fma(r0, wk, a0);
                a1 = f2fma(r1, wk, a1);
                a2 = f2fma(r2, wk, a2);
                a3 = f2fma(r3, wk, a3);
                r0 = r1; r1 = r2; r2 = r3;
            }
            float2 v0 = upk(a0), v1 = upk(a1), v2 = upk(a2), v3 = upk(a3);
            float4 A0 = {elu1(v0.x), elu1(v1.x), elu1(v2.x), elu1(v3.x)};
            float4 A1 = {elu1(v0.y), elu1(v1.y), elu1(v2.y), elu1(v3.y)};
            *(float4*)&hA[f0 * HS + 4*p + 4] = A0;
            *(float4*)&hA[f1 * HS + 4*p + 4] = A1;
        }
    }
    __syncwarp();

    // ---- fused depthwise K=3 (BN+ELU) + separable depthwise K=3 -> hB ----
    {
        ull db = dwbS[warp];
        ull d0 = dwpS[warp * 3 + 0], d1 = dwpS[warp * 3 + 1], d2 = dwpS[warp * 3 + 2];
        ull e0 = sdpS[warp * 3 + 0], e1 = sdpS[warp * 3 + 1], e2 = sdpS[warp * 3 + 2];
        for (int p = lane; p < 125; p += 32) {
            const float* A0 = &hA[f0 * HS + 4*p];
            const float* A1 = &hA[f1 * HS + 4*p];
            float4 q00 = *(const float4*)A0, q01 = *(const float4*)(A0 + 4), q02 = *(const float4*)(A0 + 8);
            float4 q10 = *(const float4*)A1, q11 = *(const float4*)(A1 + 4), q12 = *(const float4*)(A1 + 8);
            ull cc[8];
            cc[0] = pk(q00.z, q10.z); cc[1] = pk(q00.w, q10.w);
            cc[2] = pk(q01.x, q11.x); cc[3] = pk(q01.y, q11.y);
            cc[4] = pk(q01.z, q11.z); cc[5] = pk(q01.w, q11.w);
            cc[6] = pk(q02.x, q12.x); cc[7] = pk(q02.y, q12.y);
            ull ev[6];
            #pragma unroll
            for (int u = 0; u < 6; u++) {
                ull t = f2fma(cc[u], d0, f2fma(cc[u+1], d1, f2fma(cc[u+2], d2, db)));
                float2 w = upk(t);
                ev[u] = pk(elu1(w.x), elu1(w.y));
            }
            if (p == 0)   ev[0] = 0ull;   // dw output pad at t=-1
            if (p == 124) ev[5] = 0ull;   // dw output pad at t=500
            float2 o0, o1, o2, o3;
            {
                ull z = 0ull;
                o0 = upk(f2fma(ev[0], e0, f2fma(ev[1], e1, f2fma(ev[2], e2, z))));
                o1 = upk(f2fma(ev[1], e0, f2fma(ev[2], e1, f2fma(ev[3], e2, z))));
                o2 = upk(f2fma(ev[2], e0, f2fma(ev[3], e1, f2fma(ev[4], e2, z))));
                o3 = upk(f2fma(ev[3], e0, f2fma(ev[4], e1, f2fma(ev[5], e2, z))));
            }
            float4 B0 = {o0.x, o1.x, o2.x, o3.x};
            float4 B1 = {o0.y, o1.y, o2.y, o3.y};
            *(float4*)&hB[f0 * HS + 4*p] = B0;
            *(float4*)&hB[f1 * HS + 4*p] = B1;
        }
    }
    __syncthreads();

    // ---- pointwise 16->16 + BN + ELU + temporal mean ----
    {
        float s0 = 0.f, s1 = 0.f;
        for (int p = lane; p < 125; p += 32) {
            ull a01_0 = dup2(pb0), a23_0 = dup2(pb0);
            ull a01_1 = dup2(pb1), a23_1 = dup2(pb1);
            #pragma unroll
            for (int c = 0; c < 16; c++) {
                float4 v = *(const float4*)&hB[c * HS + 4*p];
                ull x01 = pk(v.x, v.y), x23 = pk(v.z, v.w);
                ull w0d = pw0dS[warp * 16 + c], w1d = pw1dS[warp * 16 + c];
                a01_0 = f2fma(x01, w0d, a01_0);
                a23_0 = f2fma(x23, w0d, a23_0);
                a01_1 = f2fma(x01, w1d, a01_1);
                a23_1 = f2fma(x23, w1d, a23_1);
            }
            float2 u;
            u = upk(a01_0); s0 += elu1(u.x) + elu1(u.y);
            u = upk(a23_0); s0 += elu1(u.x) + elu1(u.y);
            u = upk(a01_1); s1 += elu1(u.x) + elu1(u.y);
            u = upk(a23_1); s1 += elu1(u.x) + elu1(u.y);
        }
        #pragma unroll
        for (int o = 16; o > 0; o >>= 1) {
            s0 += __shfl_xor_sync(0xffffffffu, s0, o);
            s1 += __shfl_xor_sync(0xffffffffu, s1, o);
        }
        if (lane == 0) {
            g_feats[seq * 16 + f0] = s0 * (1.f / 500.f);
            g_feats[seq * 16 + f1] = s1 * (1.f / 500.f);
        }
    }
}

// ---------------------------------------------------------------------------
// GAT attention pass 1: normalized alpha -> al[(h*64+i)*68 + j]
// 512 threads: tid -> (ih = tid>>1, half = tid&1)
// ---------------------------------------------------------------------------
__device__ __forceinline__ void gat_alpha(const float* sv, const float* dv,
                                          const float* lM, float* al, int tid)
{
    int ih = tid >> 1, half = tid & 1;
    int i = ih >> 2, h = ih & 3;
    int j0 = half << 5;
    float di = dv[i * 4 + h];
    float e[32];
    float mx = -1e30f;
    #pragma unroll
    for (int jj = 0; jj < 32; jj++) {
        float t = di + sv[(j0 + jj) * 4 + h];
        e[jj] = (t > 0.f ? t : 0.2f * t) + lM[i * 64 + j0 + jj];
        mx = fmaxf(mx, e[jj]);
    }
    mx = fmaxf(mx, __shfl_xor_sync(0xffffffffu, mx, 1));
    float den = 0.f;
    #pragma unroll
    for (int jj = 0; jj < 32; jj++) {
        e[jj] = __expf(e[jj] - mx);
        den += e[jj];
    }
    den += __shfl_xor_sync(0xffffffffu, den, 1);
    float inv = 1.f / den;
    float* ap = &al[(h * 64 + i) * 68 + j0];
    #pragma unroll
    for (int jj = 0; jj < 32; jj += 4) {
        float4 w4 = {e[jj] * inv, e[jj+1] * inv, e[jj+2] * inv, e[jj+3] * inv};
        *(float4*)&ap[jj] = w4;
    }
}

// ---------------------------------------------------------------------------
// GAT attention pass 2: ho[i*148 + h*36 + f] = sum_j al[h,i,j] * xl[j,h,f]
// 512 threads: tid -> (ig = tid>>5 -> i0=4*ig, h = (tid>>3)&3, fq = tid&7)
// ---------------------------------------------------------------------------
__device__ __forceinline__ void gat_aggr(const float* xls, const float* al,
                                         float* ho, int tid)
{
    int ig = tid >> 5, h = (tid >> 3) & 3, fq = tid & 7;
    int i0 = ig * 4;
    float4 acc0 = {0,0,0,0}, acc1 = {0,0,0,0}, acc2 = {0,0,0,0}, acc3 = {0,0,0,0};
    const float* xbase = &xls[h * 36 + fq * 4];
    const float* abase = &al[(h * 64 + i0) * 68];
    #pragma unroll 4
    for (int jc = 0; jc < 16; jc++) {
        const float* xb = xbase + (4 * jc) * 148;
        float4 x0 = *(const float4*)xb;
        float4 x1 = *(const float4*)(xb + 148);
        float4 x2 = *(const float4*)(xb + 296);
        float4 x3 = *(const float4*)(xb + 444);
        const float* ab = abase + jc * 4;
        float4 a0 = *(const float4*)ab;
        float4 a1 = *(const float4*)(ab + 68);
        float4 a2 = *(const float4*)(ab + 136);
        float4 a3 = *(const float4*)(ab + 204);
        fma4(acc0, a0.x, x0); fma4(acc0, a0.y, x1); fma4(acc0, a0.z, x2); fma4(acc0, a0.w, x3);
        fma4(acc1, a1.x, x0); fma4(acc1, a1.y, x1); fma4(acc1, a1.z, x2); fma4(acc1, a1.w, x3);
        fma4(acc2, a2.x, x0); fma4(acc2, a2.y, x1); fma4(acc2, a2.z, x2); fma4(acc2, a2.w, x3);
        fma4(acc3, a3.x, x0); fma4(acc3, a3.y, x1); fma4(acc3, a3.z, x2); fma4(acc3, a3.w, x3);
    }
    float* hb = &ho[i0 * 148 + h * 36 + fq * 4];
    *(float4*)hb          = acc0;
    *(float4*)(hb + 148)  = acc1;
    *(float4*)(hb + 296)  = acc2;
    *(float4*)(hb + 444)  = acc3;
}

// ---------------------------------------------------------------------------
// K2: GAT layer 1 (128 blocks x 512 thr)
// ---------------------------------------------------------------------------
__global__ __launch_bounds__(512) void k2_gat1(
    const float* __restrict__ w1g,  const float* __restrict__ asrc,
    const float* __restrict__ adst, const float* __restrict__ bias,
    const float* __restrict__ bng,  const float* __restrict__ skw)
{
    extern __shared__ float sm[];
    float* fs  = sm;              // 1024
    float* Ws  = fs + 1024;       // 2048
    float* xls = Ws + 2048;       // 9472   (64 x 148; h stride 36)
    float* al  = xls + 9472;      // 17408  ((h*64+i) x 68)
    float* ho  = al + 17408;      // 9472
    float* sv  = ho + 9472;       // 256
    float* dv  = sv + 256;        // 256
    float* asr = dv + 256;        // 128
    float* ads = asr + 128;       // 128
    float* lM  = ads + 128;       // 4096
    float* skT = lM + 4096;       // 512
    float* vt  = skT + 512;       // 2048   total 46848 floats
    int tid = threadIdx.x;
    int b = blockIdx.x;

    for (int i = tid; i < 1024; i += 512) fs[i] = g_feats[b * 1024 + i];
    for (int i = tid; i < 2048; i += 512) Ws[i] = w1g[i];
    if (tid < 128) { asr[tid] = asrc[tid]; ads[tid] = adst[tid]; }
    for (int i = tid; i < 4096; i += 512) lM[i] = g_elogM[i];
    if (tid < 512) {
        int f = tid >> 4, c = tid & 15;     // skw [32][16]
        skT[c * 32 + f] = skw[tid];
    }
    __syncthreads();

    for (int idx = tid; idx < 8192; idx += 512) {
        int j = idx >> 7, col = idx & 127, h = col >> 5, f = col & 31;
        float a = 0.f;
        #pragma unroll
        for (int c = 0; c < 16; c++) a += fs[j * 16 + c] * Ws[c * 128 + col];
        xls[j * 148 + h * 36 + f] = a;
    }
    __syncthreads();

    {
        int sflag = tid >> 8, jh = tid & 255, j = jh >> 2, h = jh & 3;
        const float* av = sflag ? ads : asr;
        float a = 0.f;
        #pragma unroll
        for (int f = 0; f < 32; f++) a += xls[j * 148 + h * 36 + f] * av[h * 32 + f];
        if (sflag) dv[j * 4 + h] = a; else sv[j * 4 + h] = a;
    }
    __syncthreads();

    gat_alpha(sv, dv, lM, al, tid);
    __syncthreads();
    gat_aggr(xls, al, ho, tid);
    __syncthreads();

    for (int idx = tid; idx < 2048; idx += 512) {
        int i = idx >> 5, f = idx & 31;
        const float* hr = &ho[i * 148 + f];
        float o = 0.25f * (hr[0] + hr[36] + hr[72] + hr[108]) + bias[f];
        float sc = bng[f] * rsqrtf(bng[96 + f] + 1e-5f);
        o = (o - bng[64 + f]) * sc + bng[32 + f];
        float sk = 0.f;
        #pragma unroll
        for (int c = 0; c < 16; c++) sk += fs[i * 16 + c] * skT[c * 32 + f];
        float v = geluf(o + sk);
        g_h1[(b * 64 + i) * 32 + f] = v;
        vt[idx] = v;
    }
    __syncthreads();
    if (tid < 32) {
        float s = 0.f;
        for (int i = 0; i < 64; i++) s += vt[i * 32 + tid];
        g_ps1[b * 32 + tid] = s;
    }
}

// ---------------------------------------------------------------------------
// K4: SE-gate1 + GAT layer 2 (128 blocks x 512 thr)
// ---------------------------------------------------------------------------
__global__ __launch_bounds__(512) void k4_gat2(
    const float* __restrict__ w2g,  const float* __restrict__ asrc,
    const float* __restrict__ adst, const float* __restrict__ bias,
    const float* __restrict__ bng,  const float* __restrict__ se1a,
    const float* __restrict__ se1b)
{
    extern __shared__ float sm[];
    float* xin = sm;              // 2048
    float* Ws  = xin + 2048;      // 4096
    float* xls = Ws + 4096;       // 9472
    float* al  = xls + 9472;      // 17408
    float* ho  = al + 17408;      // 9472
    float* sv  = ho + 9472;       // 256
    float* dv  = sv + 256;        // 256
    float* asr = dv + 256;        // 128
    float* ads = asr + 128;       // 128
    float* lM  = ads + 128;       // 4096
    float* vt  = lM + 4096;       // 2048
    float* gate = vt + 2048;      // 72    total 49480 floats
    int tid = threadIdx.x;
    int b = blockIdx.x;

    if (tid < 32) {
        float s = 0.f;
        for (int bb = 0; bb < 128; bb++) s += g_ps1[bb * 32 + tid];
        gate[tid] = s * (1.f / 8192.f);
    }
    __syncthreads();
    if (tid < 8) {
        float a = 0.f;
        #pragma unroll
        for (int c = 0; c < 32; c++) a += gate[c] * se1a[tid * 32 + c];
        gate[32 + tid] = fmaxf(a, 0.f);
    }
    __syncthreads();
    if (tid < 32) {
        float a = 0.f;
        #pragma unroll
        for (int r = 0; r < 8; r++) a += gate[32 + r] * se1b[tid * 8 + r];
        gate[40 + tid] = sigm(a);
    }
    for (int i = tid; i < 4096; i += 512) Ws[i] = w2g[i];
    if (tid < 128) { asr[tid] = asrc[tid]; ads[tid] = adst[tid]; }
    for (int i = tid; i < 4096; i += 512) lM[i] = g_elogM[i];
    __syncthreads();

    for (int idx = tid; idx < 2048; idx += 512) {
        int f = idx & 31;
        xin[idx] = g_h1[b * 2048 + idx] * gate[40 + f];
    }
    __syncthreads();

    for (int idx = tid; idx < 8192; idx += 512) {
        int j = idx >> 7, col = idx & 127, h = col >> 5, f = col & 31;
        float a = 0.f;
        #pragma unroll
        for (int c = 0; c < 32; c++) a += xin[j * 32 + c] * Ws[c * 128 + col];
        xls[j * 148 + h * 36 + f] = a;
    }
    __syncthreads();

    {
        int sflag = tid >> 8, jh = tid & 255, j = jh >> 2, h = jh & 3;
        const float* av = sflag ? ads : asr;
        float a = 0.f;
        #pragma unroll
        for (int f = 0; f < 32; f++) a += xls[j * 148 + h * 36 + f] * av[h * 32 + f];
        if (sflag) dv[j * 4 + h] = a; else sv[j * 4 + h] = a;
    }
    __syncthreads();

    gat_alpha(sv, dv, lM, al, tid);
    __syncthreads();
    gat_aggr(xls, al, ho, tid);
    __syncthreads();

    for (int idx = tid; idx < 2048; idx += 512) {
        int i = idx >> 5, f = idx & 31;
        const float* hr = &ho[i * 148 + f];
        float o = 0.25f * (hr[0] + hr[36] + hr[72] + hr[108]) + bias[f];
        float sc = bng[f] * rsqrtf(bng[96 + f] + 1e-5f);
        o = (o - bng[64 + f]) * sc + bng[32 + f];
        float v = geluf(o + xin[idx]);
        g_h2[(b * 64 + i) * 32 + f] = v;
        vt[idx] = v;
    }
    __syncthreads();
    if (tid < 32) {
        float s = 0.f;
        for (int i = 0; i < 64; i++) s += vt[i * 32 + tid];
        g_ps2[b * 32 + tid] = s;
    }
}

// ---------------------------------------------------------------------------
// K6: SE-gate2 + node pooling + classifier
// ---------------------------------------------------------------------------
__global__ void k6_out(const float* __restrict__ se2a, const float* __restrict__ se2b,
                       const float* __restrict__ clfw, const float* __restrict__ clfb,
                       float* __restrict__ out)
{
    __shared__ float m[32], t1[8];
    int f = threadIdx.x;
    int b = blockIdx.x;
    float s = 0.f;
    for (int bb = 0; bb < 128; bb++) s += g_ps2[bb * 32 + f];
    m[f] = s * (1.f / 8192.f);
    __syncwarp();
    if (f < 8) {
        float a = 0.f;
        #pragma unroll
        for (int c = 0; c < 32; c++) a += m[c] * se2a[f * 32 + c];
        t1[f] = fmaxf(a, 0.f);
    }
    __syncwarp();
    float a = 0.f;
    #pragma unroll
    for (int r = 0; r < 8; r++) a += t1[r] * se2b[f * 8 + r];
    float gg = sigm(a);

    float acc = 0.f;
    const float* hp = g_h2 + b * 2048;
    for (int i = 0; i < 64; i++) acc += hp[i * 32 + f];
    float pooled = acc * gg * (1.f / 64.f);
    float r0 = pooled * clfw[f];
    float r1 = pooled * clfw[32 + f];
    #pragma unroll
    for (int o = 16; o > 0; o >>= 1) {
        r0 += __shfl_xor_sync(0xffffffffu, r0, o);
        r1 += __shfl_xor_sync(0xffffffffu, r1, o);
    }
    if (f == 0) {
        out[b * 2 + 0] = r0 + clfb[0];
        out[b * 2 + 1] = r1 + clfb[1];
    }
}

// ---------------------------------------------------------------------------
extern "C" void kernel_launch(void* const* d_in, const int* in_sizes, int n_in,
                              void* d_out, int out_size)
{
    const float* x    = (const float*)d_in[0];
    const int*   ei   = (const int*)  d_in[1];
    const float* c1w  = (const float*)d_in[2];
    const float* bn1  = (const float*)d_in[3];
    const float* dww  = (const float*)d_in[4];
    const float* bn2  = (const float*)d_in[5];
    const float* sdww = (const float*)d_in[6];
    const float* spww = (const float*)d_in[7];
    const float* bn3  = (const float*)d_in[8];
    const float* nemb = (const float*)d_in[9];
    const float* g1w  = (const float*)d_in[10];
    const float* g1as = (const float*)d_in[11];
    const float* g1ad = (const float*)d_in[12];
    const float* g1b  = (const float*)d_in[13];
    const float* bng1 = (const float*)d_in[14];
    const float* sk1  = (const float*)d_in[15];
    const float* se1a = (const float*)d_in[16];
    const float* se1b = (const float*)d_in[17];
    const float* g2w  = (const float*)d_in[18];
    const float* g2as = (const float*)d_in[19];
    const float* g2ad = (const float*)d_in[20];
    const float* g2b  = (const float*)d_in[21];
    const float* bng2 = (const float*)d_in[22];
    const float* se2a = (const float*)d_in[23];
    const float* se2b = (const float*)d_in[24];
    const float* clfw = (const float*)d_in[25];
    const float* clfb = (const float*)d_in[26];
    float* out = (float*)d_out;

    const int SM1 = 17952 * 4;   // 71,808 B
    const int SM2 = 46848 * 4;   // 187,392 B
    const int SM4 = 49480 * 4;   // 197,920 B
    cudaFuncSetAttribute(k1_feat, cudaFuncAttributeMaxDynamicSharedMemorySize, SM1);
    cudaFuncSetAttribute(k2_gat1, cudaFuncAttributeMaxDynamicSharedMemorySize, SM2);
    cudaFuncSetAttribute(k4_gat2, cudaFuncAttributeMaxDynamicSharedMemorySize, SM4);

    k0_graph<<<1, 256>>>(nemb, ei);
    k1_feat<<<NSEQ, 256, SM1>>>(x, c1w, bn1, dww, bn2, sdww, spww, bn3);
    k2_gat1<<<128, 512, SM2>>>(g1w, g1as, g1ad, g1b, bng1, sk1);
    k4_gat2<<<128, 512, SM4>>>(g2w, g2as, g2ad, g2b, bng2, se1a, se1b);
    k6_out<<<128, 32>>>(se2a, se2b, clfw, clfb, out);
}